// round 10
// baseline (speedup 1.0000x reference)
#include <cuda_runtime.h>

#define NITER 25
#define SIGMA 0.1f
#define BIGF  1000000000000.0f
#define LAM_FLOOR 1e-32f
#define PIV_FLOOR 1e-30f

__global__ void __launch_bounds__(256, 1) lcp_kernel(
    const float2* __restrict__ pv,
    const float*  __restrict__ mu_p,
    float2*       __restrict__ out,
    int n)
{
    int i = blockIdx.x * blockDim.x + threadIdx.x;
    if (i >= n) return;

    const float mu = *mu_p;
    float2 v = pv[i];

    // q = -prev_vels + [-2, 1]  (MASS = 1)
    float q0 = -v.x - 2.0f;
    float q1 = -v.y + 1.0f;

    float z0 = -q0, z1 = -q1;
    float lam0 = 1.f, lam1 = 1.f, lam2 = 1.f, lam3 = 1.f;
    float s0 = 1.f, s1 = 1.f, s2 = 1.f, s3 = 1.f;

    // G rows: (0,-1),(1,0),(-1,0),(0,0)
    // F rows: (0,0,0,0),(0,0,0,1),(0,0,0,1),(mu,-1,-1,0)
    #pragma unroll 1
    for (int it = 0; it < NITER; ++it) {
        // r_dual = z + q + lam@G ;  lam@G = (lam1 - lam2, -lam0)
        float rd0 = z0 + q0 + (lam1 - lam2);
        float rd1 = z1 + q1 - lam0;

        // r_pri = z@G^T + s - lam@F^T
        float rp0 = -z1 + s0;
        float rp1 =  z0 + s1 - lam3;
        float rp2 = -z0 + s2 - lam3;
        float rp3 =  s3 - (mu * lam0 - lam1 - lam2);

        // t = SIGMA * mean(s*lam)
        float sl0 = s0*lam0, sl1 = s1*lam1, sl2 = s2*lam2, sl3 = s3*lam3;
        float t = SIGMA * 0.25f * (sl0 + sl1 + sl2 + sl3);

        // Guarded reciprocals (same guards as the passing R6 kernel)
        float il0 = 1.0f / fmaxf(lam0, LAM_FLOOR);
        float il1 = 1.0f / fmaxf(lam1, LAM_FLOOR);
        float il2 = 1.0f / fmaxf(lam2, LAM_FLOOR);
        float il3 = 1.0f / fmaxf(lam3, LAM_FLOOR);
        float D0 = s0*il0, D1 = s1*il1, D2 = s2*il2, D3 = s3*il3;
        float rcl0 = (sl0 - t) * il0;
        float rcl1 = (sl1 - t) * il1;
        float rcl2 = (sl2 - t) * il2;
        float rcl3 = (sl3 - t) * il3;

        // The reference 6x6 LU provably does NOT pivot-swap in stages 0 and 1
        // (pivot magnitude 1 vs candidates <= 1 under strict '>'), and their
        // elimination multipliers are exactly +/-1. Applying those two static
        // stages symbolically leaves this 4x5 augmented system (rows 2..5,
        // cols 2..6 of the reference-transformed matrix, values identical):
        float S[4][5] = {
            { -(1.0f+D0),  0.f,         0.f,        0.f, -rp0 + rcl0 - rd1 },
            {  0.f,       -(1.0f+D1),   1.f,       -1.f, -rp1 + rcl1 + rd0 },
            {  0.f,        1.f,        -(1.0f+D2), -1.f, -rp2 + rcl2 - rd0 },
            { -mu,         1.f,         1.f,       -D3,  -rp3 + rcl3       }
        };

        // Partial-pivot LU on 4x5 (same compare-swap, pivot floor and
        // zero-guard discipline as the passing kernel).
        float ip[4];
        #pragma unroll
        for (int k = 0; k < 4; ++k) {
            #pragma unroll
            for (int r2 = k + 1; r2 < 4; ++r2) {
                bool sw = fabsf(S[r2][k]) > fabsf(S[k][k]);
                #pragma unroll
                for (int j = k; j < 5; ++j) {
                    float hk = S[k][j], hi = S[r2][j];
                    S[k][j]  = sw ? hi : hk;
                    S[r2][j] = sw ? hk : hi;
                }
            }
            float piv = S[k][k];
            float apiv = fmaxf(fabsf(piv), PIV_FLOOR);
            piv = (piv < 0.0f) ? -apiv : apiv;
            float ipk = 1.0f / piv;
            ip[k] = ipk;
            #pragma unroll
            for (int r2 = k + 1; r2 < 4; ++r2) {
                float num = S[r2][k];
                float m = (num == 0.0f) ? 0.0f : num * ipk;
                #pragma unroll
                for (int j = k + 1; j < 5; ++j)
                    S[r2][j] -= m * S[k][j];
            }
        }

        // Back substitution (reuse saved pivot reciprocals -> no divides)
        float l3 =  S[3][4] * ip[3];
        float l2 = (S[2][4] - S[2][3]*l3) * ip[2];
        float l1 = (S[1][4] - S[1][2]*l2 - S[1][3]*l3) * ip[1];
        float l0 = (S[0][4] - S[0][1]*l1 - S[0][2]*l2 - S[0][3]*l3) * ip[0];

        // Back-sub through the two static stages:
        float dz1 = -rd1 + l0;
        float dz0 = -rd0 - l1 + l2;

        // ds = -r_pri - dz@G^T + dlam@F^T
        float ds0 = -rp0 + dz1;
        float ds1 = -rp1 - dz0 + l3;
        float ds2 = -rp2 + dz0 + l3;
        float ds3 = -rp3 + mu * l0 - l1 - l2;

        // Fraction-to-boundary via division-free champion (num, den) tracking.
        // ratio_i = v_i / (-dv_i) for dv_i < -1e-12; min tracked by exact-range
        // cross-multiplication. nums pre-scaled by 2^50 (exact) keeps all
        // products within fp32 normal range.
        float ca = BIGF * 0x1p50f;   // scaled champion numerator
        float cb = 1.0f;             // champion denominator
        {
            float vv[8]  = { lam0, lam1, lam2, lam3, s0, s1, s2, s3 };
            float dd[8]  = { l0, l1, l2, l3, ds0, ds1, ds2, ds3 };
            #pragma unroll
            for (int k = 0; k < 8; ++k) {
                float b = -dd[k];
                float a = vv[k] * 0x1p50f;
                bool better = (dd[k] < -1e-12f) && (a * cb < ca * b);
                ca = better ? a : ca;
                cb = better ? b : cb;
            }
        }
        float alpha = fminf(1.0f, 0.99f * ((ca / cb) * 0x1p-50f));

        z0 += alpha * dz0;  z1 += alpha * dz1;
        lam0 += alpha * l0; lam1 += alpha * l1; lam2 += alpha * l2; lam3 += alpha * l3;
        s0 += alpha * ds0;  s1 += alpha * ds1;  s2 += alpha * ds2;  s3 += alpha * ds3;
    }

    out[i] = make_float2(z0, z1);
}

extern "C" void kernel_launch(void* const* d_in, const int* in_sizes, int n_in,
                              void* d_out, int out_size) {
    // mu has exactly 1 element; prev_vels has 2*B elements.
    int idx_pv = 0, idx_mu = 1;
    if (n_in >= 2 && in_sizes[0] < in_sizes[1]) { idx_pv = 1; idx_mu = 0; }

    const float2* pv = (const float2*)d_in[idx_pv];
    const float*  mu = (const float*)d_in[idx_mu];
    float2* out = (float2*)d_out;
    int n = in_sizes[idx_pv] / 2;
    int threads = 256;
    int blocks = (n + threads - 1) / threads;
    lcp_kernel<<<blocks, threads>>>(pv, mu, out, n);
}

// round 15
// speedup vs baseline: 1.1704x; 1.1704x over previous
#include <cuda_runtime.h>

#define NITER 25
#define SIGMA 0.1f
#define BIGF  1000000000000.0f
#define LAM_FLOOR 1e-32f
#define PIV_FLOOR 1e-30f

// sign-preserving magnitude floor for pivots (R10 guard, unchanged)
__device__ __forceinline__ float sfloor(float x) {
    float ax = fmaxf(fabsf(x), PIV_FLOOR);
    return (x < 0.0f) ? -ax : ax;
}

__global__ void __launch_bounds__(128, 1) lcp_kernel(
    const float2* __restrict__ pv,
    const float*  __restrict__ mu_p,
    float2*       __restrict__ out,
    int n)
{
    int i = blockIdx.x * blockDim.x + threadIdx.x;
    if (i >= n) return;

    const float mu = *mu_p;
    float2 v = pv[i];

    // q = -prev_vels + [-2, 1]  (MASS = 1)
    float q0 = -v.x - 2.0f;
    float q1 = -v.y + 1.0f;

    float z0 = -q0, z1 = -q1;
    float lam0 = 1.f, lam1 = 1.f, lam2 = 1.f, lam3 = 1.f;
    float s0 = 1.f, s1 = 1.f, s2 = 1.f, s3 = 1.f;

    #pragma unroll 1
    for (int it = 0; it < NITER; ++it) {
        // r_dual = z + q + lam@G ;  lam@G = (lam1 - lam2, -lam0)
        float rd0 = z0 + q0 + (lam1 - lam2);
        float rd1 = z1 + q1 - lam0;

        // r_pri = z@G^T + s - lam@F^T
        float rp0 = -z1 + s0;
        float rp1 =  z0 + s1 - lam3;
        float rp2 = -z0 + s2 - lam3;
        float rp3 =  s3 - (mu * lam0 - lam1 - lam2);

        // t = SIGMA * mean(s*lam)
        float sl0 = s0*lam0, sl1 = s1*lam1, sl2 = s2*lam2, sl3 = s3*lam3;
        float t = SIGMA * 0.25f * (sl0 + sl1 + sl2 + sl3);

        // Guarded IEEE reciprocals (exact R10 arithmetic)
        float il0 = 1.0f / fmaxf(lam0, LAM_FLOOR);
        float il1 = 1.0f / fmaxf(lam1, LAM_FLOOR);
        float il2 = 1.0f / fmaxf(lam2, LAM_FLOOR);
        float il3 = 1.0f / fmaxf(lam3, LAM_FLOOR);
        float D0 = s0*il0, D1 = s1*il1, D2 = s2*il2, D3 = s3*il3;
        float rcl0 = (sl0 - t) * il0;
        float rcl1 = (sl1 - t) * il1;
        float rcl2 = (sl2 - t) * il2;
        float rcl3 = (sl3 - t) * il3;

        // 4x5 system after the two provably-static LU stages of the 6x6:
        float S[4][5] = {
            { -(1.0f+D0),  0.f,         0.f,        0.f, -rp0 + rcl0 - rd1 },
            {  0.f,       -(1.0f+D1),   1.f,       -1.f, -rp1 + rcl1 + rd0 },
            {  0.f,        1.f,        -(1.0f+D2), -1.f, -rp2 + rcl2 - rd0 },
            { -mu,         1.f,         1.f,       -D3,  -rp3 + rcl3       }
        };
        float ip0, ip1, ip2, ip3;

        // ---- Stage 0: rows 1,2 have structural zeros in col 0 => under
        // strict '>' only row3 can displace row0; only row3 needs elimination.
        // (Arithmetically identical to R10's sequential compare-swap loop.)
        {
            bool sw = fabsf(S[3][0]) > fabsf(S[0][0]);
            #pragma unroll
            for (int j = 0; j < 5; ++j) {
                float a = S[0][j], b = S[3][j];
                S[0][j] = sw ? b : a;
                S[3][j] = sw ? a : b;
            }
            ip0 = 1.0f / sfloor(S[0][0]);
            float num = S[3][0];
            float m = (num == 0.0f) ? 0.0f : num * ip0;   // |m| <= 1
            #pragma unroll
            for (int j = 1; j < 5; ++j) S[3][j] -= m * S[0][j];
        }

        // ---- Stage 1: |S[2][1]| = 1 can never beat 1+D1 under strict '>';
        // only row3 can displace row1. Eliminate rows 2,3.
        {
            bool sw = fabsf(S[3][1]) > fabsf(S[1][1]);
            #pragma unroll
            for (int j = 1; j < 5; ++j) {
                float a = S[1][j], b = S[3][j];
                S[1][j] = sw ? b : a;
                S[3][j] = sw ? a : b;
            }
            ip1 = 1.0f / sfloor(S[1][1]);
            float n2 = S[2][1], n3 = S[3][1];
            float m2 = (n2 == 0.0f) ? 0.0f : n2 * ip1;
            float m3 = (n3 == 0.0f) ? 0.0f : n3 * ip1;
            #pragma unroll
            for (int j = 2; j < 5; ++j) {
                S[2][j] -= m2 * S[1][j];
                S[3][j] -= m3 * S[1][j];
            }
        }

        // ---- Stage 2: full compare-swap rows 2,3; eliminate row3.
        {
            bool sw = fabsf(S[3][2]) > fabsf(S[2][2]);
            #pragma unroll
            for (int j = 2; j < 5; ++j) {
                float a = S[2][j], b = S[3][j];
                S[2][j] = sw ? b : a;
                S[3][j] = sw ? a : b;
            }
            ip2 = 1.0f / sfloor(S[2][2]);
            float num = S[3][2];
            float m = (num == 0.0f) ? 0.0f : num * ip2;
            #pragma unroll
            for (int j = 3; j < 5; ++j) S[3][j] -= m * S[2][j];
        }

        // ---- Stage 3
        ip3 = 1.0f / sfloor(S[3][3]);

        // Back substitution (reciprocal reuse, no divides)
        float l3 =  S[3][4] * ip3;
        float l2 = (S[2][4] - S[2][3]*l3) * ip2;
        float l1 = (S[1][4] - S[1][2]*l2 - S[1][3]*l3) * ip1;
        float l0 = (S[0][4] - S[0][1]*l1 - S[0][2]*l2 - S[0][3]*l3) * ip0;

        // Back-sub through the two static stages:
        float dz1 = -rd1 + l0;
        float dz0 = -rd0 - l1 + l2;

        // ds = -r_pri - dz@G^T + dlam@F^T
        float ds0 = -rp0 + dz1;
        float ds1 = -rp1 - dz0 + l3;
        float ds2 = -rp2 + dz0 + l3;
        float ds3 = -rp3 + mu * l0 - l1 - l2;

        // Fraction-to-boundary: division-free champion (num, den) tracking.
        float ca = BIGF * 0x1p50f;
        float cb = 1.0f;
        {
            float vv[8] = { lam0, lam1, lam2, lam3, s0, s1, s2, s3 };
            float dd[8] = { l0, l1, l2, l3, ds0, ds1, ds2, ds3 };
            #pragma unroll
            for (int k = 0; k < 8; ++k) {
                float b = -dd[k];
                float a = vv[k] * 0x1p50f;
                bool better = (dd[k] < -1e-12f) && (a * cb < ca * b);
                ca = better ? a : ca;
                cb = better ? b : cb;
            }
        }
        float alpha = fminf(1.0f, 0.99f * ((ca / cb) * 0x1p-50f));

        z0 += alpha * dz0;  z1 += alpha * dz1;
        lam0 += alpha * l0; lam1 += alpha * l1; lam2 += alpha * l2; lam3 += alpha * l3;
        s0 += alpha * ds0;  s1 += alpha * ds1;  s2 += alpha * ds2;  s3 += alpha * ds3;
    }

    out[i] = make_float2(z0, z1);
}

extern "C" void kernel_launch(void* const* d_in, const int* in_sizes, int n_in,
                              void* d_out, int out_size) {
    // mu has exactly 1 element; prev_vels has 2*B elements.
    int idx_pv = 0, idx_mu = 1;
    if (n_in >= 2 && in_sizes[0] < in_sizes[1]) { idx_pv = 1; idx_mu = 0; }

    const float2* pv = (const float2*)d_in[idx_pv];
    const float*  mu = (const float*)d_in[idx_mu];
    float2* out = (float2*)d_out;
    int n = in_sizes[idx_pv] / 2;
    int threads = 128;
    int blocks = (n + threads - 1) / threads;
    lcp_kernel<<<blocks, threads>>>(pv, mu, out, n);
}

// round 16
// speedup vs baseline: 1.5039x; 1.2849x over previous
#include <cuda_runtime.h>

#define NITER 25
#define SIGMA 0.1f
#define BIGF  1000000000000.0f
#define LAM_FLOOR 1e-32f
#define PIV_FLOOR 1e-30f

// Newton-refined reciprocal: MUFU.RCP + 2 FMA, error <= ~1 ulp vs IEEE.
// Valid for normal-range inputs (all call sites are floored/bounded).
__device__ __forceinline__ float rcp_nr(float x) {
    float y;
    asm("rcp.approx.ftz.f32 %0, %1;" : "=f"(y) : "f"(x));
    float e = fmaf(-x, y, 1.0f);
    return fmaf(y, e, y);
}

// sign-preserving magnitude floor for pivots (R10 guard, unchanged)
__device__ __forceinline__ float sfloor(float x) {
    float ax = fmaxf(fabsf(x), PIV_FLOOR);
    return (x < 0.0f) ? -ax : ax;
}

__global__ void __launch_bounds__(128, 1) lcp_kernel(
    const float2* __restrict__ pv,
    const float*  __restrict__ mu_p,
    float2*       __restrict__ out,
    int n)
{
    int i = blockIdx.x * blockDim.x + threadIdx.x;
    if (i >= n) return;

    const float mu = *mu_p;
    float2 v = pv[i];

    // q = -prev_vels + [-2, 1]  (MASS = 1)
    float q0 = -v.x - 2.0f;
    float q1 = -v.y + 1.0f;

    float z0 = -q0, z1 = -q1;
    float lam0 = 1.f, lam1 = 1.f, lam2 = 1.f, lam3 = 1.f;
    float s0 = 1.f, s1 = 1.f, s2 = 1.f, s3 = 1.f;

    #pragma unroll 1
    for (int it = 0; it < NITER; ++it) {
        // r_dual = z + q + lam@G ;  lam@G = (lam1 - lam2, -lam0)
        float rd0 = z0 + q0 + (lam1 - lam2);
        float rd1 = z1 + q1 - lam0;

        // r_pri = z@G^T + s - lam@F^T
        float rp0 = -z1 + s0;
        float rp1 =  z0 + s1 - lam3;
        float rp2 = -z0 + s2 - lam3;
        float rp3 =  s3 - (mu * lam0 - lam1 - lam2);

        // t = SIGMA * mean(s*lam)
        float sl0 = s0*lam0, sl1 = s1*lam1, sl2 = s2*lam2, sl3 = s3*lam3;
        float t = SIGMA * 0.25f * (sl0 + sl1 + sl2 + sl3);

        // Guarded Newton-refined reciprocals (il <= ~1e32, never inf)
        float il0 = rcp_nr(fmaxf(lam0, LAM_FLOOR));
        float il1 = rcp_nr(fmaxf(lam1, LAM_FLOOR));
        float il2 = rcp_nr(fmaxf(lam2, LAM_FLOOR));
        float il3 = rcp_nr(fmaxf(lam3, LAM_FLOOR));
        float D0 = s0*il0, D1 = s1*il1, D2 = s2*il2, D3 = s3*il3;
        float rcl0 = (sl0 - t) * il0;
        float rcl1 = (sl1 - t) * il1;
        float rcl2 = (sl2 - t) * il2;
        float rcl3 = (sl3 - t) * il3;

        // 4x5 system after the two provably-static LU stages of the 6x6:
        float S[4][5] = {
            { -(1.0f+D0),  0.f,         0.f,        0.f, -rp0 + rcl0 - rd1 },
            {  0.f,       -(1.0f+D1),   1.f,       -1.f, -rp1 + rcl1 + rd0 },
            {  0.f,        1.f,        -(1.0f+D2), -1.f, -rp2 + rcl2 - rd0 },
            { -mu,         1.f,         1.f,       -D3,  -rp3 + rcl3       }
        };
        float ip0, ip1, ip2, ip3;

        // ---- Stage 0: rows 1,2 have structural zeros in col 0 => under
        // strict '>' only row3 can displace row0; only row3 needs elimination.
        {
            bool sw = fabsf(S[3][0]) > fabsf(S[0][0]);
            #pragma unroll
            for (int j = 0; j < 5; ++j) {
                float a = S[0][j], b = S[3][j];
                S[0][j] = sw ? b : a;
                S[3][j] = sw ? a : b;
            }
            ip0 = rcp_nr(sfloor(S[0][0]));
            float num = S[3][0];
            float m = (num == 0.0f) ? 0.0f : num * ip0;   // |m| <= 1
            #pragma unroll
            for (int j = 1; j < 5; ++j) S[3][j] -= m * S[0][j];
        }

        // ---- Stage 1: |S[2][1]| = 1 can never beat 1+D1 under strict '>';
        // only row3 can displace row1. Eliminate rows 2,3.
        {
            bool sw = fabsf(S[3][1]) > fabsf(S[1][1]);
            #pragma unroll
            for (int j = 1; j < 5; ++j) {
                float a = S[1][j], b = S[3][j];
                S[1][j] = sw ? b : a;
                S[3][j] = sw ? a : b;
            }
            ip1 = rcp_nr(sfloor(S[1][1]));
            float n2 = S[2][1], n3 = S[3][1];
            float m2 = (n2 == 0.0f) ? 0.0f : n2 * ip1;
            float m3 = (n3 == 0.0f) ? 0.0f : n3 * ip1;
            #pragma unroll
            for (int j = 2; j < 5; ++j) {
                S[2][j] -= m2 * S[1][j];
                S[3][j] -= m3 * S[1][j];
            }
        }

        // ---- Stage 2: full compare-swap rows 2,3; eliminate row3.
        {
            bool sw = fabsf(S[3][2]) > fabsf(S[2][2]);
            #pragma unroll
            for (int j = 2; j < 5; ++j) {
                float a = S[2][j], b = S[3][j];
                S[2][j] = sw ? b : a;
                S[3][j] = sw ? a : b;
            }
            ip2 = rcp_nr(sfloor(S[2][2]));
            float num = S[3][2];
            float m = (num == 0.0f) ? 0.0f : num * ip2;
            #pragma unroll
            for (int j = 3; j < 5; ++j) S[3][j] -= m * S[2][j];
        }

        // ---- Stage 3
        ip3 = rcp_nr(sfloor(S[3][3]));

        // Back substitution (reciprocal reuse, no divides)
        float l3 =  S[3][4] * ip3;
        float l2 = (S[2][4] - S[2][3]*l3) * ip2;
        float l1 = (S[1][4] - S[1][2]*l2 - S[1][3]*l3) * ip1;
        float l0 = (S[0][4] - S[0][1]*l1 - S[0][2]*l2 - S[0][3]*l3) * ip0;

        // Back-sub through the two static stages:
        float dz1 = -rd1 + l0;
        float dz0 = -rd0 - l1 + l2;

        // ds = -r_pri - dz@G^T + dlam@F^T
        float ds0 = -rp0 + dz1;
        float ds1 = -rp1 - dz0 + l3;
        float ds2 = -rp2 + dz0 + l3;
        float ds3 = -rp3 + mu * l0 - l1 - l2;

        // Fraction-to-boundary: division-free champion (num, den) tracking.
        float ca = BIGF * 0x1p50f;
        float cb = 1.0f;
        {
            float vv[8] = { lam0, lam1, lam2, lam3, s0, s1, s2, s3 };
            float dd[8] = { l0, l1, l2, l3, ds0, ds1, ds2, ds3 };
            #pragma unroll
            for (int k = 0; k < 8; ++k) {
                float b = -dd[k];
                float a = vv[k] * 0x1p50f;
                bool better = (dd[k] < -1e-12f) && (a * cb < ca * b);
                ca = better ? a : ca;
                cb = better ? b : cb;
            }
        }
        float alpha = fminf(1.0f, 0.99f * ((ca * rcp_nr(cb)) * 0x1p-50f));

        z0 += alpha * dz0;  z1 += alpha * dz1;
        lam0 += alpha * l0; lam1 += alpha * l1; lam2 += alpha * l2; lam3 += alpha * l3;
        s0 += alpha * ds0;  s1 += alpha * ds1;  s2 += alpha * ds2;  s3 += alpha * ds3;
    }

    out[i] = make_float2(z0, z1);
}

extern "C" void kernel_launch(void* const* d_in, const int* in_sizes, int n_in,
                              void* d_out, int out_size) {
    // mu has exactly 1 element; prev_vels has 2*B elements.
    int idx_pv = 0, idx_mu = 1;
    if (n_in >= 2 && in_sizes[0] < in_sizes[1]) { idx_pv = 1; idx_mu = 0; }

    const float2* pv = (const float2*)d_in[idx_pv];
    const float*  mu = (const float*)d_in[idx_mu];
    float2* out = (float2*)d_out;
    int n = in_sizes[idx_pv] / 2;
    int threads = 128;
    int blocks = (n + threads - 1) / threads;
    lcp_kernel<<<blocks, threads>>>(pv, mu, out, n);
}